// round 1
// baseline (speedup 1.0000x reference)
#include <cuda_runtime.h>

// ---------------------------------------------------------------------------
// Sparse 3D submanifold U-block, fp32, gather-GEMM-scatter formulation.
// Scratch: static device pool (no allocations). All launches on stream 0.
// ---------------------------------------------------------------------------

#define MAXN 48128  // n0 = 4*12000 = 48000; small slack

__device__ float g_pool[8][(size_t)MAXN * 64];

static inline int ceil_div(int a, int b) { return (a + b - 1) / b; }

// ---------------------------------------------------------------------------
// BN + ReLU:  y = relu((x - m) * g * rsqrt(v + eps) + b), params stacked [4,C]
// ---------------------------------------------------------------------------
__global__ void bnrelu_kernel(const float* __restrict__ x,
                              const float* __restrict__ p,
                              float* __restrict__ y, int total, int C) {
    int i = blockIdx.x * blockDim.x + threadIdx.x;
    if (i >= total) return;
    int c = i % C;
    float g = p[c], be = p[C + c], m = p[2 * C + c], v = p[3 * C + c];
    float s = g * rsqrtf(v + 1e-4f);
    float val = (x[i] - m) * s + be;
    y[i] = val > 0.f ? val : 0.f;
}

// ---------------------------------------------------------------------------
// Concat [a | b] along channels (32 + 32 -> 64)
// ---------------------------------------------------------------------------
__global__ void concat_kernel(const float* __restrict__ a,
                              const float* __restrict__ b,
                              float* __restrict__ y, int n0) {
    int idx = blockIdx.x * blockDim.x + threadIdx.x;
    if (idx >= n0 * 64) return;
    int i = idx >> 6, c = idx & 63;
    y[idx] = (c < 32) ? a[i * 32 + c] : b[i * 32 + (c - 32)];
}

// ---------------------------------------------------------------------------
// Dense shortcut GEMM: y[n0,32] = x[n0,64] @ W[64,32]
// ---------------------------------------------------------------------------
__global__ void linear64to32_kernel(const float* __restrict__ x,
                                    const float* __restrict__ W,
                                    float* __restrict__ y, int n0) {
    int idx = blockIdx.x * blockDim.x + threadIdx.x;
    if (idx >= n0 * 32) return;
    int i = idx >> 5, d = idx & 31;
    const float* xr = x + (size_t)i * 64;
    float acc = 0.f;
#pragma unroll
    for (int c = 0; c < 64; c++) acc = fmaf(xr[c], W[c * 32 + d], acc);
    y[idx] = acc;
}

// ---------------------------------------------------------------------------
// Scatter sparse conv:  out[pout[k,p]] += x[pin[k,p]] @ W[k]   (atomicAdd)
//   - pads (pin == nin) are a suffix of each k-list -> whole-tile early exit
//   - 128-pair tile staged in SMEM, register-tiled micro-GEMM 8r x DT
// ---------------------------------------------------------------------------
template <int CIN, int COUT>
__global__ void conv_scatter(const float* __restrict__ x,
                             const float* __restrict__ W,
                             const int* __restrict__ pin,
                             const int* __restrict__ pout,
                             int P, int nin,
                             float* __restrict__ out) {
    constexpr int TP = 128;
    constexpr int DT = (COUT >= 64) ? 4 : 2;  // 16 d-groups either way

    const int k = blockIdx.y;
    const int base = blockIdx.x * TP;
    const int tid = threadIdx.x;

    const int* pinK = pin + (size_t)k * P;
    const int* poutK = pout + (size_t)k * P;

    // pads are a suffix: if the first pair of the tile is a pad, all are.
    if (pinK[base] == nin) return;

    extern __shared__ char smraw[];
    float* sG = (float*)smraw;            // TP * CIN
    float* sW = sG + TP * CIN;            // CIN * COUT (row-major, same as W)
    int* sIn = (int*)(sW + CIN * COUT);   // TP
    int* sO = sIn + TP;                   // TP

    const float* Wk = W + (size_t)k * (CIN * COUT);
    for (int i = tid; i < CIN * COUT; i += 256) sW[i] = Wk[i];

    for (int r = tid; r < TP; r += 256) {
        int p = base + r;
        int idx = (p < P) ? pinK[p] : nin;
        sIn[r] = idx;
        sO[r] = (idx == nin) ? -1 : poutK[p];
    }
    __syncthreads();

    constexpr int Q = CIN / 4;
    for (int t = tid; t < TP * Q; t += 256) {
        int r = t / Q, q = t - r * Q;
        int idx = sIn[r];
        float4 v;
        if (idx < nin)
            v = *(const float4*)(x + (size_t)idx * CIN + q * 4);
        else
            v = make_float4(0.f, 0.f, 0.f, 0.f);
        *(float4*)(sG + r * CIN + q * 4) = v;
    }
    __syncthreads();

    const int dg = tid & 15;
    const int rg = tid >> 4;
    const int d0 = dg * DT;
    const int r0 = rg * 8;

    float acc[8][DT];
#pragma unroll
    for (int j = 0; j < 8; j++)
#pragma unroll
        for (int u = 0; u < DT; u++) acc[j][u] = 0.f;

#pragma unroll
    for (int c = 0; c < CIN; c += 4) {
        float4 g4[8];
#pragma unroll
        for (int j = 0; j < 8; j++)
            g4[j] = *(const float4*)(sG + (r0 + j) * CIN + c);
#pragma unroll
        for (int cc = 0; cc < 4; cc++) {
            float w[DT];
#pragma unroll
            for (int u = 0; u < DT; u++) w[u] = sW[(c + cc) * COUT + d0 + u];
#pragma unroll
            for (int j = 0; j < 8; j++) {
                float g = (cc == 0) ? g4[j].x
                        : (cc == 1) ? g4[j].y
                        : (cc == 2) ? g4[j].z
                                    : g4[j].w;
#pragma unroll
                for (int u = 0; u < DT; u++)
                    acc[j][u] = fmaf(g, w[u], acc[j][u]);
            }
        }
    }

#pragma unroll
    for (int j = 0; j < 8; j++) {
        int o = sO[r0 + j];
        if (o >= 0) {
            float* op = out + (size_t)o * COUT + d0;
#pragma unroll
            for (int u = 0; u < DT; u++) atomicAdd(op + u, acc[j][u]);
        }
    }
}

// dynamic smem bytes for conv_scatter<CIN,COUT>
static inline int conv_smem(int CIN, int COUT) {
    return (128 * CIN + CIN * COUT) * 4 + 128 * 8;
}

extern "C" void kernel_launch(void* const* d_in, const int* in_sizes, int n_in,
                              void* d_out, int out_size) {
    const float* feats   = (const float*)d_in[0];
    const float* res0_W  = (const float*)d_in[1];
    const float* res0_bn = (const float*)d_in[2];
    const float* down_bn = (const float*)d_in[3];
    const float* down_W  = (const float*)d_in[4];
    const float* res1_W  = (const float*)d_in[5];
    const float* res1_bn = (const float*)d_in[6];
    const float* up_bn   = (const float*)d_in[7];
    const float* up_W    = (const float*)d_in[8];
    const float* t0_bn1  = (const float*)d_in[9];
    const float* t0_W1   = (const float*)d_in[10];
    const float* t0_bn2  = (const float*)d_in[11];
    const float* t0_W2   = (const float*)d_in[12];
    const float* t0_Wsc  = (const float*)d_in[13];
    const float* t1_W    = (const float*)d_in[14];
    const float* t1_bn   = (const float*)d_in[15];
    const int* s0i = (const int*)d_in[16];
    const int* s0o = (const int*)d_in[17];
    const int* s1i = (const int*)d_in[18];
    const int* s1o = (const int*)d_in[19];
    const int* dni = (const int*)d_in[20];
    const int* dno = (const int*)d_in[21];

    const int n0 = in_sizes[0] / 32;
    const int P0 = in_sizes[16] / 27;
    const int P1 = in_sizes[18] / 27;
    const int Pd = in_sizes[20] / 8;
    // the (0,0,0) offset pairs every point with itself, so the padded width
    // of the subm1 list equals n1 exactly — lets us avoid a D2H sync.
    const int n1 = P1;

    float* pool = nullptr;
    cudaGetSymbolAddress((void**)&pool, g_pool);
    const size_t slot = (size_t)MAXN * 64;
    float* S0 = pool + 0 * slot;
    float* S1 = pool + 1 * slot;
    float* S2 = pool + 2 * slot;
    float* S3 = pool + 3 * slot;
    float* S4 = pool + 4 * slot;
    float* S5 = pool + 5 * slot;
    float* S6 = pool + 6 * slot;
    float* S7 = pool + 7 * slot;

    cudaFuncSetAttribute(conv_scatter<32, 32>,
                         cudaFuncAttributeMaxDynamicSharedMemorySize, conv_smem(32, 32));
    cudaFuncSetAttribute(conv_scatter<32, 64>,
                         cudaFuncAttributeMaxDynamicSharedMemorySize, conv_smem(32, 64));
    cudaFuncSetAttribute(conv_scatter<64, 32>,
                         cudaFuncAttributeMaxDynamicSharedMemorySize, conv_smem(64, 32));
    cudaFuncSetAttribute(conv_scatter<64, 64>,
                         cudaFuncAttributeMaxDynamicSharedMemorySize, conv_smem(64, 64));

    const int BT = 256;
    dim3 g0(ceil_div(P0, 128), 27);
    dim3 g1(ceil_div(P1, 128), 27);
    dim3 gd(ceil_div(Pd, 128), 8);

#define BNRELU(src, prm, dst, n, C) \
    bnrelu_kernel<<<ceil_div((n) * (C), BT), BT>>>(src, prm, dst, (n) * (C), C)

    // ---------------- level 0: 2x residual blocks (C32) ----------------
    cudaMemcpyAsync(S0, feats, (size_t)n0 * 32 * 4, cudaMemcpyDeviceToDevice);
    float* X = S0;
    float* O = S3;
    for (int i = 0; i < 2; i++) {
        BNRELU(X, res0_bn + (i * 2 + 0) * 128, S1, n0, 32);
        cudaMemsetAsync(S2, 0, (size_t)n0 * 32 * 4);
        conv_scatter<32, 32><<<g0, BT, conv_smem(32, 32)>>>(
            S1, res0_W + (size_t)(i * 2 + 0) * 27 * 1024, s0i, s0o, P0, n0, S2);
        BNRELU(S2, res0_bn + (i * 2 + 1) * 128, S1, n0, 32);
        cudaMemcpyAsync(O, X, (size_t)n0 * 32 * 4, cudaMemcpyDeviceToDevice);
        conv_scatter<32, 32><<<g0, BT, conv_smem(32, 32)>>>(
            S1, res0_W + (size_t)(i * 2 + 1) * 27 * 1024, s0i, s0o, P0, n0, O);
        float* t = X; X = O; O = t;
    }
    // X == identity (S0 after two swaps)

    // ---------------- downsample: conv 32->64, K=8 ----------------
    BNRELU(X, down_bn, S1, n0, 32);
    cudaMemsetAsync(S4, 0, (size_t)n1 * 64 * 4);
    conv_scatter<32, 64><<<gd, BT, conv_smem(32, 64)>>>(
        S1, down_W, dni, dno, Pd, n0, S4);

    // ---------------- level 1: 2x residual blocks (C64) ----------------
    float* X1 = S4;
    float* O1 = S7;
    for (int i = 0; i < 2; i++) {
        BNRELU(X1, res1_bn + (i * 2 + 0) * 256, S5, n1, 64);
        cudaMemsetAsync(S6, 0, (size_t)n1 * 64 * 4);
        conv_scatter<64, 64><<<g1, BT, conv_smem(64, 64)>>>(
            S5, res1_W + (size_t)(i * 2 + 0) * 27 * 4096, s1i, s1o, P1, n1, S6);
        BNRELU(S6, res1_bn + (i * 2 + 1) * 256, S5, n1, 64);
        cudaMemcpyAsync(O1, X1, (size_t)n1 * 64 * 4, cudaMemcpyDeviceToDevice);
        conv_scatter<64, 64><<<g1, BT, conv_smem(64, 64)>>>(
            S5, res1_W + (size_t)(i * 2 + 1) * 27 * 4096, s1i, s1o, P1, n1, O1);
        float* t = X1; X1 = O1; O1 = t;
    }

    // ---------------- upsample (transposed): conv 64->32, K=8 ----------------
    BNRELU(X1, up_bn, S5, n1, 64);
    cudaMemsetAsync(S6, 0, (size_t)n0 * 32 * 4);
    conv_scatter<64, 32><<<gd, BT, conv_smem(64, 32)>>>(
        S5, up_W, dno, dni, Pd, n1, S6);  // swapped in/out lists

    // ---------------- concat + tail0 ----------------
    // XC = [identity | dec]  -> S5  (n0 x 64)
    concat_kernel<<<ceil_div(n0 * 64, BT), BT>>>(X, S6, S5, n0);
    BNRELU(S5, t0_bn1, S1, n0, 64);
    cudaMemsetAsync(S2, 0, (size_t)n0 * 32 * 4);
    conv_scatter<64, 32><<<g0, BT, conv_smem(64, 32)>>>(
        S1, t0_W1, s0i, s0o, P0, n0, S2);
    BNRELU(S2, t0_bn2, S1, n0, 32);
    // O (the free level-0 slot) = XC @ Wsc, then conv adds on top
    linear64to32_kernel<<<ceil_div(n0 * 32, BT), BT>>>(S5, t0_Wsc, O, n0);
    conv_scatter<32, 32><<<g0, BT, conv_smem(32, 32)>>>(
        S1, t0_W2, s0i, s0o, P0, n0, O);
    float* XT = O;  // tail0 output

    // ---------------- tail1: residual block (C32), fused into d_out ----------
    BNRELU(XT, t1_bn + 0, S1, n0, 32);
    cudaMemsetAsync(S2, 0, (size_t)n0 * 32 * 4);
    conv_scatter<32, 32><<<g0, BT, conv_smem(32, 32)>>>(
        S1, t1_W + 0, s0i, s0o, P0, n0, S2);
    BNRELU(S2, t1_bn + 128, S1, n0, 32);
    cudaMemcpyAsync(d_out, XT, (size_t)n0 * 32 * 4, cudaMemcpyDeviceToDevice);
    conv_scatter<32, 32><<<g0, BT, conv_smem(32, 32)>>>(
        S1, t1_W + (size_t)27 * 1024, s0i, s0o, P0, n0, (float*)d_out);

#undef BNRELU
}